// round 9
// baseline (speedup 1.0000x reference)
#include <cuda_runtime.h>
#include <cuda_bf16.h>
#include <cstdint>

// ---------------------------------------------------------------- constants
#define N_ROWS   65536
#define DIMV     128
#define KCODES   1024
#define RPB      128                  // rows per block (M)
#define CPC      64                   // codes per chunk (N)
#define NCH      (KCODES / CPC)       // 16
#define TPB      256
#define NBLOCKS  (N_ROWS / RPB)       // 512

// padded bf16 row: 136 elems = 272 B = 17 x 16B granules (conflict-free ldmatrix)
#define ROWB     272
#define B_SPLIT  (CPC * ROWB)         // 17408
#define B_BUF    (2 * B_SPLIT)        // 34816 (2 limbs)
#define ET_SPLIT (KCODES * ROWB)      // 278528

// smem layout (no A staging anymore — A lives in registers)
#define SM_B     0
#define SM_RE    (2 * B_BUF)                      // 69632
#define SM_RX    (SM_RE + KCODES * 4)             // 73728
#define SM_REDD  (SM_RX + RPB * 4)                // 74240
#define SM_REDI  (SM_REDD + RPB * 4 * 4)          // 76288
#define SM_BEST  (SM_REDI + RPB * 4 * 4)          // 78336
#define SM_LOSS  (SM_BEST + RPB * 4)              // 78848
#define SM_RED2  (SM_LOSS + 8 * 8)                // 78912
#define SM_FLAG  (SM_RED2 + 8 * 4)                // 78944
#define SMEM_TOTAL (SM_FLAG + 16)                 // 78960

// ---------------------------------------------------------------- scratch
__device__ float        g_re[KCODES];
__device__ int          g_counts[KCODES];
__device__ double       g_loss;
__device__ unsigned int g_ticket;
// padded bf16 codebook limbs: [2][1024][136] bf16
__device__ __align__(16) unsigned char g_eTp[2u * ET_SPLIT];

// ---------------------------------------------------------------- helpers
__device__ __forceinline__ uint32_t smem_u32(const void* p) {
    uint32_t a;
    asm("{ .reg .u64 t; cvta.to.shared.u64 t, %1; cvt.u32.u64 %0, t; }"
        : "=r"(a) : "l"(p));
    return a;
}
static __device__ __forceinline__ void cp_async16(uint32_t dst, const void* src) {
    asm volatile("cp.async.cg.shared.global [%0], [%1], 16;\n" :: "r"(dst), "l"(src));
}
#define CP_COMMIT() asm volatile("cp.async.commit_group;\n" ::: "memory")
#define CP_WAIT1()  asm volatile("cp.async.wait_group 1;\n" ::: "memory")

#define LDSM4(r, addr) \
    asm volatile("ldmatrix.sync.aligned.m8n8.x4.shared.b16 {%0,%1,%2,%3}, [%4];" \
        : "=r"((r)[0]), "=r"((r)[1]), "=r"((r)[2]), "=r"((r)[3]) : "r"(addr))

#define MMA16816(c, a, b0, b1) \
    asm volatile("mma.sync.aligned.m16n8k16.row.col.f32.bf16.bf16.f32 " \
        "{%0,%1,%2,%3}, {%4,%5,%6,%7}, {%8,%9}, {%0,%1,%2,%3};" \
        : "+f"((c)[0]), "+f"((c)[1]), "+f"((c)[2]), "+f"((c)[3]) \
        : "r"((a)[0]), "r"((a)[1]), "r"((a)[2]), "r"((a)[3]), "r"(b0), "r"(b1))

// ordering: (dA,iA) < (dB,iB)  [strict, lowest index on ties]
static __device__ __forceinline__ bool lt(float dA, int iA, float dB, int iB) {
    return dA < dB || (dA == dB && iA < iB);
}
static __device__ __forceinline__ void ins2(float d, int i,
                                            float& bD, int& bI, float& sD, int& sI) {
    if (lt(d, i, bD, bI)) { sD = bD; sI = bI; bD = d; bI = i; }
    else if (lt(d, i, sD, sI)) { sD = d; sI = i; }
}

// bf16 dual-limb sp of a scalar (x = limb0 + limb1 + O(2^-18 x))
static __device__ __forceinline__ __nv_bfloat16 split_bf(float f, int sp) {
    __nv_bfloat16 h1 = __float2bfloat16_rn(f);
    if (sp == 0) return h1;
    return __float2bfloat16_rn(__fadd_rn(f, -__bfloat162float(h1)));
}
// both limbs of a float2, packed as bf16x2 words (low = .x)
static __device__ __forceinline__ void pack_limbs(float2 v, uint32_t& p0, uint32_t& p1) {
    __nv_bfloat16 hx = __float2bfloat16_rn(v.x);
    __nv_bfloat16 hy = __float2bfloat16_rn(v.y);
    __nv_bfloat16 lx = __float2bfloat16_rn(__fadd_rn(v.x, -__bfloat162float(hx)));
    __nv_bfloat16 ly = __float2bfloat16_rn(__fadd_rn(v.y, -__bfloat162float(hy)));
    p0 = (uint32_t)__bfloat16_as_ushort(hx) | ((uint32_t)__bfloat16_as_ushort(hy) << 16);
    p1 = (uint32_t)__bfloat16_as_ushort(lx) | ((uint32_t)__bfloat16_as_ushort(ly) << 16);
}

// ---------------------------------------------------------------- prep
__global__ void vq_prep(const float* __restrict__ emb) {
    int g = blockIdx.x * blockDim.x + threadIdx.x;   // 0..2047
    int k = g >> 1, half = g & 1;
    const float4* e4 = (const float4*)(emb + (size_t)k * DIMV + half * 64);
    unsigned char* base = g_eTp + (size_t)k * ROWB + half * 128;
    double s = 0.0;
#pragma unroll
    for (int i = 0; i < 16; ++i) {
        float4 v = e4[i];
        s += (double)__fmul_rn(v.x, v.x) + (double)__fmul_rn(v.y, v.y)
           + (double)__fmul_rn(v.z, v.z) + (double)__fmul_rn(v.w, v.w);
#pragma unroll
        for (int sp = 0; sp < 2; ++sp) {
            unsigned char* p = base + (size_t)sp * ET_SPLIT + i * 8;
            *(__nv_bfloat162*)(p)     = __halves2bfloat162(split_bf(v.x, sp), split_bf(v.y, sp));
            *(__nv_bfloat162*)(p + 4) = __halves2bfloat162(split_bf(v.z, sp), split_bf(v.w, sp));
        }
    }
    s += __shfl_xor_sync(0xffffffffu, s, 1);
    if (!half) { g_re[k] = (float)s; g_counts[k] = 0; }
    if (g == 0) { g_loss = 0.0; g_ticket = 0u; }
}

// ---------------------------------------------------------------- main
__global__ __launch_bounds__(TPB, 1)
void vq_main(const float* __restrict__ x, const float* __restrict__ emb,
             float* __restrict__ out, int out_size) {
    extern __shared__ __align__(16) char sm[];
    float*  sRE   = (float*)(sm + SM_RE);
    float*  sRX   = (float*)(sm + SM_RX);
    float*  sRedD = (float*)(sm + SM_REDD);
    int*    sRedI = (int*)  (sm + SM_REDI);
    int*    sBest = (int*)  (sm + SM_BEST);
    double* sLoss = (double*)(sm + SM_LOSS);
    float*  sRed2 = (float*)(sm + SM_RED2);
    unsigned int* sFlag = (unsigned int*)(sm + SM_FLAG);

    const uint32_t smb = smem_u32(sm);
    const int tid = threadIdx.x, wid = tid >> 5, l = tid & 31;
    const int wm = wid & 3, wn = wid >> 2;          // 4 x 2 warp grid
    const size_t row0 = (size_t)blockIdx.x * RPB;

    // ---- prefetch B chunks 0,1 immediately (overlap with A-frag loads) ----
    {
        const char* srcb = (const char*)g_eTp;
#pragma unroll
        for (int c = 0; c < 2; ++c) {
            uint32_t dst = smb + SM_B + c * B_BUF;
            const char* src = srcb + (size_t)c * CPC * ROWB;
            for (int i = tid; i < B_BUF / 16; i += TPB) {
                int s = i / (B_SPLIT / 16), r = i - s * (B_SPLIT / 16);
                cp_async16(dst + i * 16, src + (size_t)s * ET_SPLIT + r * 16);
            }
            CP_COMMIT();
        }
    }

    // ---- A fragments: load straight from gmem, split to 2 limbs in regs ----
    // PTX m16n8k16 A layout: lane l owns (r,c),(r+8,c),(r,c+8),(r+8,c+8),
    // r = l>>2, c = 2*(l&3); per reg: bf16x2 (low = col c).
    uint32_t Areg[2][2][8][4];   // [limb][mi][ks][frag]
#pragma unroll
    for (int mi = 0; mi < 2; ++mi) {
        const float* xr0 = x + (row0 + wm * 32 + mi * 16 + (l >> 2)) * DIMV;
        const float* xr1 = xr0 + 8 * DIMV;
#pragma unroll
        for (int ks = 0; ks < 8; ++ks) {
            int c0 = ks * 16 + (l & 3) * 2;
            float2 v0 = *(const float2*)(xr0 + c0);
            float2 v1 = *(const float2*)(xr1 + c0);
            float2 v2 = *(const float2*)(xr0 + c0 + 8);
            float2 v3 = *(const float2*)(xr1 + c0 + 8);
            pack_limbs(v0, Areg[0][mi][ks][0], Areg[1][mi][ks][0]);
            pack_limbs(v1, Areg[0][mi][ks][1], Areg[1][mi][ks][1]);
            pack_limbs(v2, Areg[0][mi][ks][2], Areg[1][mi][ks][2]);
            pack_limbs(v3, Areg[0][mi][ks][3], Areg[1][mi][ks][3]);
        }
    }

    // ---- fp64 row norms + code norms into smem ----
    if (tid < RPB) {
        const float4* xr = (const float4*)(x + (row0 + tid) * DIMV);
        double s = 0.0;
#pragma unroll 8
        for (int i = 0; i < 32; ++i) {
            float4 v = xr[i];
            s += (double)__fmul_rn(v.x, v.x) + (double)__fmul_rn(v.y, v.y)
               + (double)__fmul_rn(v.z, v.z) + (double)__fmul_rn(v.w, v.w);
        }
        sRX[tid] = (float)s;
    }
    for (int i = tid; i < KCODES; i += TPB) sRE[i] = g_re[i];
    __syncthreads();   // sRX/sRE visible

    float rxv[4];
#pragma unroll
    for (int s = 0; s < 4; ++s) rxv[s] = sRX[wm * 32 + (l >> 2) + s * 8];

    uint32_t bOff[2][2];
#pragma unroll
    for (int sp = 0; sp < 2; ++sp)
#pragma unroll
        for (int g = 0; g < 2; ++g)
            bOff[sp][g] = sp * B_SPLIT
                        + (wn * 32 + g * 16 + (l & 7) + ((l >> 4) & 1) * 8) * ROWB
                        + ((l >> 3) & 1) * 16;

    float bestD[4], secD[4];
    int   bestI[4], secI[4];
#pragma unroll
    for (int s = 0; s < 4; ++s) {
        bestD[s] = secD[s] = 3.402823466e38f;
        bestI[s] = secI[s] = 0x7fffffff;
    }

    // 3 limb passes: (x1,e1), (x1,e2), (x2,e1)
    const int PA[3] = {0, 0, 1}, PB[3] = {0, 1, 0};

#pragma unroll 1
    for (int c = 0; c < NCH; ++c) {
        CP_WAIT1();
        __syncthreads();                 // buf (c&1) ready for all
        uint32_t bB = smb + SM_B + (c & 1) * B_BUF;

        float acc[2][4][4];
#pragma unroll
        for (int mi = 0; mi < 2; ++mi)
#pragma unroll
            for (int ni = 0; ni < 4; ++ni)
#pragma unroll
                for (int q = 0; q < 4; ++q) acc[mi][ni][q] = 0.f;

#pragma unroll
        for (int ks = 0; ks < 8; ++ks) {
            uint32_t B[2][2][4];
#pragma unroll
            for (int sp = 0; sp < 2; ++sp)
#pragma unroll
                for (int g = 0; g < 2; ++g) LDSM4(B[sp][g], bB + bOff[sp][g] + ks * 32);
#pragma unroll
            for (int p = 0; p < 3; ++p) {
#pragma unroll
                for (int mi = 0; mi < 2; ++mi)
#pragma unroll
                    for (int ni = 0; ni < 4; ++ni) {
                        int g = ni >> 1, h = (ni & 1) * 2;
                        MMA16816(acc[mi][ni], Areg[PA[p]][mi][ks],
                                 B[PB[p]][g][h], B[PB[p]][g][h + 1]);
                    }
            }
        }

        // epilogue: reference-rounded distance + running top-2
        int cb = c * CPC + wn * 32;
#pragma unroll
        for (int mi = 0; mi < 2; ++mi) {
#pragma unroll
            for (int ni = 0; ni < 4; ++ni) {
                int code = cb + ni * 8 + 2 * (l & 3);
                float re0 = sRE[code], re1 = sRE[code + 1];
                int s0 = mi * 2, s1 = mi * 2 + 1;
                float d;
                d = __fadd_rn(__fadd_rn(rxv[s0], re0), __fmul_rn(acc[mi][ni][0], -2.0f));
                ins2(d, code,     bestD[s0], bestI[s0], secD[s0], secI[s0]);
                d = __fadd_rn(__fadd_rn(rxv[s0], re1), __fmul_rn(acc[mi][ni][1], -2.0f));
                ins2(d, code + 1, bestD[s0], bestI[s0], secD[s0], secI[s0]);
                d = __fadd_rn(__fadd_rn(rxv[s1], re0), __fmul_rn(acc[mi][ni][2], -2.0f));
                ins2(d, code,     bestD[s1], bestI[s1], secD[s1], secI[s1]);
                d = __fadd_rn(__fadd_rn(rxv[s1], re1), __fmul_rn(acc[mi][ni][3], -2.0f));
                ins2(d, code + 1, bestD[s1], bestI[s1], secD[s1], secI[s1]);
            }
        }
        __syncthreads();                 // all readers done with buf (c&1)
        if (c + 2 < NCH) {
            uint32_t dst = smb + SM_B + (c & 1) * B_BUF;
            const char* src = (const char*)g_eTp + (size_t)(c + 2) * CPC * ROWB;
            for (int i = tid; i < B_BUF / 16; i += TPB) {
                int s = i / (B_SPLIT / 16), r = i - s * (B_SPLIT / 16);
                cp_async16(dst + i * 16, src + (size_t)s * ET_SPLIT + r * 16);
            }
            CP_COMMIT();
        }
    }

    // ---- top-2 merge across lanes (bfly over l&3) ----
#pragma unroll
    for (int s = 0; s < 4; ++s) {
#pragma unroll
        for (int m = 1; m <= 2; m <<= 1) {
            float obD = __shfl_xor_sync(0xffffffffu, bestD[s], m);
            int   obI = __shfl_xor_sync(0xffffffffu, bestI[s], m);
            float osD = __shfl_xor_sync(0xffffffffu, secD[s], m);
            int   osI = __shfl_xor_sync(0xffffffffu, secI[s], m);
            ins2(obD, obI, bestD[s], bestI[s], secD[s], secI[s]);
            ins2(osD, osI, bestD[s], bestI[s], secD[s], secI[s]);
        }
    }
    if ((l & 3) == 0) {
#pragma unroll
        for (int s = 0; s < 4; ++s) {
            int r = wm * 32 + (l >> 2) + s * 8;
            sRedD[(r * 2 + wn) * 2]     = bestD[s];
            sRedD[(r * 2 + wn) * 2 + 1] = secD[s];
            sRedI[(r * 2 + wn) * 2]     = bestI[s];
            sRedI[(r * 2 + wn) * 2 + 1] = secI[s];
        }
    }
    __syncthreads();

    // ---- per-row final: EXACT fp32 recheck of ALL 4 candidates ----
    if (tid < RPB) {
        const float4* xr = (const float4*)(x + (row0 + tid) * DIMV);
        float rx = sRX[tid];
        float bD = 3.402823466e38f;
        int   bi = 0x7fffffff;
#pragma unroll
        for (int t = 0; t < 4; ++t) {
            int cd = sRedI[tid * 4 + t];
            const float4* er = (const float4*)(emb + (size_t)cd * DIMV);
            float a0 = 0.f, a1 = 0.f, a2 = 0.f, a3 = 0.f;
#pragma unroll 8
            for (int j = 0; j < 32; ++j) {
                float4 xv = xr[j], ev = er[j];
                a0 = __fmaf_rn(xv.x, ev.x, a0);
                a1 = __fmaf_rn(xv.y, ev.y, a1);
                a2 = __fmaf_rn(xv.z, ev.z, a2);
                a3 = __fmaf_rn(xv.w, ev.w, a3);
            }
            float m = __fadd_rn(__fadd_rn(a0, a1), __fadd_rn(a2, a3));
            float d = __fadd_rn(__fadd_rn(rx, sRE[cd]), __fmul_rn(m, -2.0f));
            if (lt(d, cd, bD, bi)) { bD = d; bi = cd; }
        }
        sBest[tid] = bi;
        atomicAdd(&g_counts[bi], 1);
    }
    __syncthreads();

    // ---- fused output: STE-rounded gather + fp64 loss partial ----
    double ls = 0.0;
    {
        const float4* xin4 = (const float4*)(x + row0 * DIMV);
        float4*       o4   = (float4*)(out + row0 * DIMV);
        const float4* e4   = (const float4*)emb;
        for (int i = tid; i < RPB * (DIMV / 4); i += TPB) {
            int rr  = i >> 5;
            int col = i & 31;
            float4 q  = e4[(size_t)sBest[rr] * 32 + col];
            float4 xv = xin4[i];
            float4 o;
            o.x = __fadd_rn(xv.x, __fadd_rn(q.x, -xv.x));
            o.y = __fadd_rn(xv.y, __fadd_rn(q.y, -xv.y));
            o.z = __fadd_rn(xv.z, __fadd_rn(q.z, -xv.z));
            o.w = __fadd_rn(xv.w, __fadd_rn(q.w, -xv.w));
            o4[i] = o;
            double dx = (double)q.x - xv.x, dy = (double)q.y - xv.y;
            double dz = (double)q.z - xv.z, dw = (double)q.w - xv.w;
            ls += dx * dx + dy * dy + dz * dz + dw * dw;
        }
    }
#pragma unroll
    for (int o = 16; o > 0; o >>= 1) ls += __shfl_down_sync(0xffffffffu, ls, o);
    if (l == 0) sLoss[wid] = ls;
    __syncthreads();
    if (tid == 0) {
        double t = 0.0;
#pragma unroll
        for (int i = 0; i < 8; ++i) t += sLoss[i];
        atomicAdd(&g_loss, t);
        // ticket: last block finalizes
        __threadfence();
        unsigned int tk = atomicAdd(&g_ticket, 1u);
        sFlag[0] = (tk == (unsigned int)(NBLOCKS - 1)) ? 1u : 0u;
    }
    __syncthreads();

    // ---- fused finalize (last block only): perplexity + loss scalars ----
    if (sFlag[0]) {
        __threadfence();
        float acc = 0.f;
        for (int k = tid; k < KCODES; k += TPB) {
            float p = (float)__ldcg(&g_counts[k]) * (1.0f / (float)N_ROWS);
            acc += p * logf(p + 1e-10f);
        }
#pragma unroll
        for (int o = 16; o > 0; o >>= 1) acc += __shfl_down_sync(0xffffffffu, acc, o);
        if (l == 0) sRed2[wid] = acc;
        __syncthreads();
        if (tid == 0) {
            float s = 0.f;
#pragma unroll
            for (int i = 0; i < 8; ++i) s += sRed2[i];
            double lv = __ldcg(&g_loss);
            out[out_size - 2] = (float)(1.25 * (lv / (double)(N_ROWS * DIMV)));
            out[out_size - 1] = expf(-s);
        }
    }
}

// ----------------------------------------------------------------
extern "C" void kernel_launch(void* const* d_in, const int* in_sizes, int n_in,
                              void* d_out, int out_size) {
    const float* x   = (const float*)d_in[0];
    const float* emb = (const float*)d_in[1];
    float*       out = (float*)d_out;
    (void)in_sizes; (void)n_in;

    cudaFuncSetAttribute(vq_main, cudaFuncAttributeMaxDynamicSharedMemorySize,
                         SMEM_TOTAL);

    vq_prep<<<8, 256>>>(emb);
    vq_main<<<NBLOCKS, TPB, SMEM_TOTAL>>>(x, emb, out, out_size);
}

// round 10
// speedup vs baseline: 1.3246x; 1.3246x over previous
#include <cuda_runtime.h>
#include <cuda_bf16.h>
#include <cstdint>

// ---------------------------------------------------------------- constants
#define N_ROWS   65536
#define DIMV     128
#define KCODES   1024
#define RPB      128                  // rows per block (M)
#define CPC      32                   // codes per chunk (N)
#define NCH      (KCODES / CPC)       // 32
#define TPB      256
#define NBLOCKS  (N_ROWS / RPB)       // 512

// padded bf16 row: 136 elems = 272 B = 17 x 16B granules (conflict-free ldmatrix)
#define ROWB     272
#define XA_SPLIT (RPB * ROWB)         // 34816
#define B_SPLIT  (CPC * ROWB)         // 8704
#define B_BUF    (2 * B_SPLIT)        // 17408 (2 limbs)
#define ET_SPLIT (KCODES * ROWB)      // 278528

// smem layout (total 113264 -> 2 blocks/SM)
#define SM_XA    0
#define SM_B     (2 * XA_SPLIT)                   // 69632
#define SM_RE    (SM_B + 2 * B_BUF)               // 104448
#define SM_RX    (SM_RE + KCODES * 4)             // 108544
#define SM_REDD  (SM_RX + RPB * 4)                // 109056
#define SM_REDI  (SM_REDD + RPB * 4 * 4)          // 111104
#define SM_LOSS  (SM_REDI + RPB * 4 * 4)          // 113152
#define SM_RED2  (SM_LOSS + 8 * 8)                // 113216
#define SM_FLAG  (SM_RED2 + 8 * 4)                // 113248
#define SMEM_TOTAL (SM_FLAG + 16)                 // 113264

// ---------------------------------------------------------------- scratch
__device__ float        g_re[KCODES];
__device__ int          g_counts[KCODES];
__device__ double       g_loss;
__device__ unsigned int g_ticket;
// padded bf16 codebook limbs: [2][1024][136] bf16
__device__ __align__(16) unsigned char g_eTp[2u * ET_SPLIT];

// ---------------------------------------------------------------- helpers
__device__ __forceinline__ uint32_t smem_u32(const void* p) {
    uint32_t a;
    asm("{ .reg .u64 t; cvta.to.shared.u64 t, %1; cvt.u32.u64 %0, t; }"
        : "=r"(a) : "l"(p));
    return a;
}
static __device__ __forceinline__ void cp_async16(uint32_t dst, const void* src) {
    asm volatile("cp.async.cg.shared.global [%0], [%1], 16;\n" :: "r"(dst), "l"(src));
}
#define CP_COMMIT() asm volatile("cp.async.commit_group;\n" ::: "memory")
#define CP_WAIT1()  asm volatile("cp.async.wait_group 1;\n" ::: "memory")

#define LDSM4(r, addr) \
    asm volatile("ldmatrix.sync.aligned.m8n8.x4.shared.b16 {%0,%1,%2,%3}, [%4];" \
        : "=r"((r)[0]), "=r"((r)[1]), "=r"((r)[2]), "=r"((r)[3]) : "r"(addr))

#define MMA16816(c, a, b0, b1) \
    asm volatile("mma.sync.aligned.m16n8k16.row.col.f32.bf16.bf16.f32 " \
        "{%0,%1,%2,%3}, {%4,%5,%6,%7}, {%8,%9}, {%0,%1,%2,%3};" \
        : "+f"((c)[0]), "+f"((c)[1]), "+f"((c)[2]), "+f"((c)[3]) \
        : "r"((a)[0]), "r"((a)[1]), "r"((a)[2]), "r"((a)[3]), "r"(b0), "r"(b1))

// ordering: (dA,iA) < (dB,iB)  [strict, lowest index on ties]
static __device__ __forceinline__ bool lt(float dA, int iA, float dB, int iB) {
    return dA < dB || (dA == dB && iA < iB);
}
static __device__ __forceinline__ void ins2(float d, int i,
                                            float& bD, int& bI, float& sD, int& sI) {
    if (lt(d, i, bD, bI)) { sD = bD; sI = bI; bD = d; bI = i; }
    else if (lt(d, i, sD, sI)) { sD = d; sI = i; }
}

// bf16 dual-limb sp of a scalar (x = limb0 + limb1 + O(2^-18 x))
static __device__ __forceinline__ __nv_bfloat16 split_bf(float f, int sp) {
    __nv_bfloat16 h1 = __float2bfloat16_rn(f);
    if (sp == 0) return h1;
    return __float2bfloat16_rn(__fadd_rn(f, -__bfloat162float(h1)));
}

// ---------------------------------------------------------------- prep
__global__ void vq_prep(const float* __restrict__ emb) {
    int g = blockIdx.x * blockDim.x + threadIdx.x;   // 0..2047
    int k = g >> 1, half = g & 1;
    const float4* e4 = (const float4*)(emb + (size_t)k * DIMV + half * 64);
    unsigned char* base = g_eTp + (size_t)k * ROWB + half * 128;
    double s = 0.0;
#pragma unroll
    for (int i = 0; i < 16; ++i) {
        float4 v = e4[i];
        s += (double)__fmul_rn(v.x, v.x) + (double)__fmul_rn(v.y, v.y)
           + (double)__fmul_rn(v.z, v.z) + (double)__fmul_rn(v.w, v.w);
#pragma unroll
        for (int sp = 0; sp < 2; ++sp) {
            unsigned char* p = base + (size_t)sp * ET_SPLIT + i * 8;
            *(__nv_bfloat162*)(p)     = __halves2bfloat162(split_bf(v.x, sp), split_bf(v.y, sp));
            *(__nv_bfloat162*)(p + 4) = __halves2bfloat162(split_bf(v.z, sp), split_bf(v.w, sp));
        }
    }
    s += __shfl_xor_sync(0xffffffffu, s, 1);
    if (!half) { g_re[k] = (float)s; g_counts[k] = 0; }
    if (g == 0) { g_loss = 0.0; g_ticket = 0u; }
}

// ---------------------------------------------------------------- main
__global__ __launch_bounds__(TPB, 2)
void vq_main(const float* __restrict__ x, const float* __restrict__ emb,
             float* __restrict__ out, int out_size) {
    extern __shared__ __align__(16) char sm[];
    float*  sRE   = (float*)(sm + SM_RE);
    float*  sRX   = (float*)(sm + SM_RX);
    float*  sRedD = (float*)(sm + SM_REDD);
    int*    sRedI = (int*)  (sm + SM_REDI);
    double* sLoss = (double*)(sm + SM_LOSS);
    float*  sRed2 = (float*)(sm + SM_RED2);
    unsigned int* sFlag = (unsigned int*)(sm + SM_FLAG);

    const uint32_t smb = smem_u32(sm);
    const int tid = threadIdx.x, wid = tid >> 5, l = tid & 31;
    const int wm = wid & 3, wn = wid >> 2;          // 4 x 2 warp grid
    const size_t row0 = (size_t)blockIdx.x * RPB;

    // ---- prefetch B chunks 0,1 ----
    {
        const char* srcb = (const char*)g_eTp;
#pragma unroll
        for (int c = 0; c < 2; ++c) {
            uint32_t dst = smb + SM_B + c * B_BUF;
            const char* src = srcb + (size_t)c * CPC * ROWB;
            for (int i = tid; i < B_BUF / 16; i += TPB) {
                int s = i / (B_SPLIT / 16), r = i - s * (B_SPLIT / 16);
                cp_async16(dst + i * 16, src + (size_t)s * ET_SPLIT + r * 16);
            }
            CP_COMMIT();
        }
    }

    // ---- stage x limbs (padded bf16) + fp64 row norms ----
    {
        int row = tid >> 1, half = tid & 1;
        const float4* xr = (const float4*)(x + (row0 + row) * DIMV + half * 64);
        char* base = sm + SM_XA + row * ROWB + half * 128;
        double s = 0.0;
#pragma unroll
        for (int i = 0; i < 16; ++i) {
            float4 v = xr[i];
            s += (double)__fmul_rn(v.x, v.x) + (double)__fmul_rn(v.y, v.y)
               + (double)__fmul_rn(v.z, v.z) + (double)__fmul_rn(v.w, v.w);
#pragma unroll
            for (int sp = 0; sp < 2; ++sp) {
                char* p = base + sp * XA_SPLIT + i * 8;
                *(__nv_bfloat162*)(p)     = __halves2bfloat162(split_bf(v.x, sp), split_bf(v.y, sp));
                *(__nv_bfloat162*)(p + 4) = __halves2bfloat162(split_bf(v.z, sp), split_bf(v.w, sp));
            }
        }
        s += __shfl_xor_sync(0xffffffffu, s, 1);
        if (!half) sRX[row] = (float)s;
    }
    for (int i = tid; i < KCODES; i += TPB) sRE[i] = g_re[i];
    __syncthreads();   // staging of A/rx visible

    float rxv[4];
#pragma unroll
    for (int s = 0; s < 4; ++s) rxv[s] = sRX[wm * 32 + (l >> 2) + s * 8];

    uint32_t aAddr[2][2];
#pragma unroll
    for (int sp = 0; sp < 2; ++sp)
#pragma unroll
        for (int mi = 0; mi < 2; ++mi)
            aAddr[sp][mi] = smb + SM_XA + sp * XA_SPLIT
                          + (wm * 32 + mi * 16 + (l & 15)) * ROWB + ((l >> 4) & 1) * 16;
    uint32_t bOff[2];
#pragma unroll
    for (int sp = 0; sp < 2; ++sp)
        bOff[sp] = sp * B_SPLIT
                 + (wn * 16 + (l & 7) + ((l >> 4) & 1) * 8) * ROWB
                 + ((l >> 3) & 1) * 16;

    float bestD[4], secD[4];
    int   bestI[4], secI[4];
#pragma unroll
    for (int s = 0; s < 4; ++s) {
        bestD[s] = secD[s] = 3.402823466e38f;
        bestI[s] = secI[s] = 0x7fffffff;
    }

    // 3 limb passes: (x1,e1), (x1,e2), (x2,e1)
    const int PA[3] = {0, 0, 1}, PB[3] = {0, 1, 0};

#pragma unroll 1
    for (int c = 0; c < NCH; ++c) {
        CP_WAIT1();
        __syncthreads();                 // buf (c&1) ready for all
        uint32_t bB = smb + SM_B + (c & 1) * B_BUF;

        float acc[2][2][4];
#pragma unroll
        for (int mi = 0; mi < 2; ++mi)
#pragma unroll
            for (int ni = 0; ni < 2; ++ni)
#pragma unroll
                for (int q = 0; q < 4; ++q) acc[mi][ni][q] = 0.f;

#pragma unroll
        for (int ks = 0; ks < 8; ++ks) {
            uint32_t A[2][2][4], B[2][4];
#pragma unroll
            for (int sp = 0; sp < 2; ++sp) {
#pragma unroll
                for (int mi = 0; mi < 2; ++mi) LDSM4(A[sp][mi], aAddr[sp][mi] + ks * 32);
                LDSM4(B[sp], bB + bOff[sp] + ks * 32);
            }
#pragma unroll
            for (int p = 0; p < 3; ++p) {
#pragma unroll
                for (int mi = 0; mi < 2; ++mi)
#pragma unroll
                    for (int ni = 0; ni < 2; ++ni)
                        MMA16816(acc[mi][ni], A[PA[p]][mi],
                                 B[PB[p]][ni * 2], B[PB[p]][ni * 2 + 1]);
            }
        }

        // epilogue: reference-rounded distance + running top-2
        int cb = c * CPC + wn * 16;
#pragma unroll
        for (int mi = 0; mi < 2; ++mi) {
#pragma unroll
            for (int ni = 0; ni < 2; ++ni) {
                int code = cb + ni * 8 + 2 * (l & 3);
                float re0 = sRE[code], re1 = sRE[code + 1];
                int s0 = mi * 2, s1 = mi * 2 + 1;
                float d;
                d = __fadd_rn(__fadd_rn(rxv[s0], re0), __fmul_rn(acc[mi][ni][0], -2.0f));
                ins2(d, code,     bestD[s0], bestI[s0], secD[s0], secI[s0]);
                d = __fadd_rn(__fadd_rn(rxv[s0], re1), __fmul_rn(acc[mi][ni][1], -2.0f));
                ins2(d, code + 1, bestD[s0], bestI[s0], secD[s0], secI[s0]);
                d = __fadd_rn(__fadd_rn(rxv[s1], re0), __fmul_rn(acc[mi][ni][2], -2.0f));
                ins2(d, code,     bestD[s1], bestI[s1], secD[s1], secI[s1]);
                d = __fadd_rn(__fadd_rn(rxv[s1], re1), __fmul_rn(acc[mi][ni][3], -2.0f));
                ins2(d, code + 1, bestD[s1], bestI[s1], secD[s1], secI[s1]);
            }
        }
        __syncthreads();                 // all readers done with buf (c&1)
        if (c + 2 < NCH) {
            uint32_t dst = smb + SM_B + (c & 1) * B_BUF;
            const char* src = (const char*)g_eTp + (size_t)(c + 2) * CPC * ROWB;
            for (int i = tid; i < B_BUF / 16; i += TPB) {
                int s = i / (B_SPLIT / 16), r = i - s * (B_SPLIT / 16);
                cp_async16(dst + i * 16, src + (size_t)s * ET_SPLIT + r * 16);
            }
            CP_COMMIT();
        }
    }

    // ---- top-2 merge across lanes (bfly over l&3) ----
#pragma unroll
    for (int s = 0; s < 4; ++s) {
#pragma unroll
        for (int m = 1; m <= 2; m <<= 1) {
            float obD = __shfl_xor_sync(0xffffffffu, bestD[s], m);
            int   obI = __shfl_xor_sync(0xffffffffu, bestI[s], m);
            float osD = __shfl_xor_sync(0xffffffffu, secD[s], m);
            int   osI = __shfl_xor_sync(0xffffffffu, secI[s], m);
            ins2(obD, obI, bestD[s], bestI[s], secD[s], secI[s]);
            ins2(osD, osI, bestD[s], bestI[s], secD[s], secI[s]);
        }
    }
    if ((l & 3) == 0) {
#pragma unroll
        for (int s = 0; s < 4; ++s) {
            int r = wm * 32 + (l >> 2) + s * 8;
            sRedD[(r * 2 + wn) * 2]     = bestD[s];
            sRedD[(r * 2 + wn) * 2 + 1] = secD[s];
            sRedI[(r * 2 + wn) * 2]     = bestI[s];
            sRedI[(r * 2 + wn) * 2 + 1] = secI[s];
        }
    }
    __syncthreads();

    // ---- per-row final: EXACT fp32 recheck of ALL 4 candidates ----
    if (tid < RPB) {
        const float4* xr = (const float4*)(x + (row0 + tid) * DIMV);
        float rx = sRX[tid];
        float bD = 3.402823466e38f;
        int   bi = 0x7fffffff;
#pragma unroll
        for (int t = 0; t < 4; ++t) {
            int cd = sRedI[tid * 4 + t];
            const float4* er = (const float4*)(emb + (size_t)cd * DIMV);
            float a0 = 0.f, a1 = 0.f, a2 = 0.f, a3 = 0.f;
#pragma unroll 8
            for (int j = 0; j < 32; ++j) {
                float4 xv = xr[j], ev = er[j];
                a0 = __fmaf_rn(xv.x, ev.x, a0);
                a1 = __fmaf_rn(xv.y, ev.y, a1);
                a2 = __fmaf_rn(xv.z, ev.z, a2);
                a3 = __fmaf_rn(xv.w, ev.w, a3);
            }
            float m = __fadd_rn(__fadd_rn(a0, a1), __fadd_rn(a2, a3));
            float d = __fadd_rn(__fadd_rn(rx, sRE[cd]), __fmul_rn(m, -2.0f));
            if (lt(d, cd, bD, bi)) { bD = d; bi = cd; }
        }
        sRedI[tid * 4] = bi;             // reuse as per-row best index
        atomicAdd(&g_counts[bi], 1);
    }
    __syncthreads();

    // ---- fused output: STE-rounded gather + fp64 loss partial ----
    double ls = 0.0;
    {
        const float4* xin4 = (const float4*)(x + row0 * DIMV);
        float4*       o4   = (float4*)(out + row0 * DIMV);
        const float4* e4   = (const float4*)emb;
        for (int i = tid; i < RPB * (DIMV / 4); i += TPB) {
            int rr  = i >> 5;
            int col = i & 31;
            float4 q  = e4[(size_t)sRedI[rr * 4] * 32 + col];
            float4 xv = xin4[i];
            float4 o;
            o.x = __fadd_rn(xv.x, __fadd_rn(q.x, -xv.x));
            o.y = __fadd_rn(xv.y, __fadd_rn(q.y, -xv.y));
            o.z = __fadd_rn(xv.z, __fadd_rn(q.z, -xv.z));
            o.w = __fadd_rn(xv.w, __fadd_rn(q.w, -xv.w));
            o4[i] = o;
            double dx = (double)q.x - xv.x, dy = (double)q.y - xv.y;
            double dz = (double)q.z - xv.z, dw = (double)q.w - xv.w;
            ls += dx * dx + dy * dy + dz * dz + dw * dw;
        }
    }
#pragma unroll
    for (int o = 16; o > 0; o >>= 1) ls += __shfl_down_sync(0xffffffffu, ls, o);
    if (l == 0) sLoss[wid] = ls;
    __syncthreads();
    if (tid == 0) {
        double t = 0.0;
#pragma unroll
        for (int i = 0; i < 8; ++i) t += sLoss[i];
        atomicAdd(&g_loss, t);
        __threadfence();
        unsigned int tk = atomicAdd(&g_ticket, 1u);
        sFlag[0] = (tk == (unsigned int)(NBLOCKS - 1)) ? 1u : 0u;
    }
    __syncthreads();

    // ---- fused finalize (last block only): perplexity + loss scalars ----
    if (sFlag[0]) {
        __threadfence();
        float acc = 0.f;
        for (int k = tid; k < KCODES; k += TPB) {
            float p = (float)__ldcg(&g_counts[k]) * (1.0f / (float)N_ROWS);
            acc += p * logf(p + 1e-10f);
        }
#pragma unroll
        for (int o = 16; o > 0; o >>= 1) acc += __shfl_down_sync(0xffffffffu, acc, o);
        if (l == 0) sRed2[wid] = acc;
        __syncthreads();
        if (tid == 0) {
            float s = 0.f;
#pragma unroll
            for (int i = 0; i < 8; ++i) s += sRed2[i];
            double lv = __ldcg(&g_loss);
            out[out_size - 2] = (float)(1.25 * (lv / (double)(N_ROWS * DIMV)));
            out[out_size - 1] = expf(-s);
        }
    }
}

// ----------------------------------------------------------------
extern "C" void kernel_launch(void* const* d_in, const int* in_sizes, int n_in,
                              void* d_out, int out_size) {
    const float* x   = (const float*)d_in[0];
    const float* emb = (const float*)d_in[1];
    float*       out = (float*)d_out;
    (void)in_sizes; (void)n_in;

    cudaFuncSetAttribute(vq_main, cudaFuncAttributeMaxDynamicSharedMemorySize,
                         SMEM_TOTAL);

    vq_prep<<<8, 256>>>(emb);
    vq_main<<<NBLOCKS, TPB, SMEM_TOTAL>>>(x, emb, out, out_size);
}

// round 11
// speedup vs baseline: 1.4165x; 1.0694x over previous
#include <cuda_runtime.h>
#include <cuda_bf16.h>
#include <cstdint>

// ---------------------------------------------------------------- constants
#define N_ROWS   65536
#define DIMV     128
#define KCODES   1024
#define RPB      128                  // rows per block (M)
#define CPC      64                   // codes per chunk (N)
#define NCH      (KCODES / CPC)       // 16
#define TPB      256
#define NBLOCKS  (N_ROWS / RPB)       // 512

// padded bf16 row: 136 elems = 272 B = 17 x 16B granules (conflict-free ldmatrix)
#define ROWB     272
#define XA_SPLIT (RPB * ROWB)         // 34816
#define B_SPLIT  (CPC * ROWB)         // 17408 per limb
#define B_BUF    (2 * B_SPLIT)        // 34816 (2 limbs, SINGLE buffer)
#define ET_SPLIT (KCODES * ROWB)      // 278528

// smem layout (total 113264 -> 2 blocks/SM)
#define SM_XA    0
#define SM_B     (2 * XA_SPLIT)                   // 69632
#define SM_RE    (SM_B + B_BUF)                   // 104448
#define SM_RX    (SM_RE + KCODES * 4)             // 108544
#define SM_REDD  (SM_RX + RPB * 4)                // 109056
#define SM_REDI  (SM_REDD + RPB * 4 * 4)          // 111104
#define SM_LOSS  (SM_REDI + RPB * 4 * 4)          // 113152
#define SM_RED2  (SM_LOSS + 8 * 8)                // 113216
#define SM_FLAG  (SM_RED2 + 8 * 4)                // 113248
#define SMEM_TOTAL (SM_FLAG + 16)                 // 113264

// ---------------------------------------------------------------- scratch
__device__ float        g_re[KCODES];
__device__ int          g_counts[KCODES];
__device__ double       g_loss;
__device__ unsigned int g_ticket;
// padded bf16 codebook limbs: [2][1024][136] bf16
__device__ __align__(16) unsigned char g_eTp[2u * ET_SPLIT];

// ---------------------------------------------------------------- helpers
__device__ __forceinline__ uint32_t smem_u32(const void* p) {
    uint32_t a;
    asm("{ .reg .u64 t; cvta.to.shared.u64 t, %1; cvt.u32.u64 %0, t; }"
        : "=r"(a) : "l"(p));
    return a;
}
static __device__ __forceinline__ void cp_async16(uint32_t dst, const void* src) {
    asm volatile("cp.async.cg.shared.global [%0], [%1], 16;\n" :: "r"(dst), "l"(src));
}
#define CP_COMMIT() asm volatile("cp.async.commit_group;\n" ::: "memory")
#define CP_WAIT0()  asm volatile("cp.async.wait_group 0;\n" ::: "memory")

#define LDSM4(r, addr) \
    asm volatile("ldmatrix.sync.aligned.m8n8.x4.shared.b16 {%0,%1,%2,%3}, [%4];" \
        : "=r"((r)[0]), "=r"((r)[1]), "=r"((r)[2]), "=r"((r)[3]) : "r"(addr))

#define MMA16816(c, a, b0, b1) \
    asm volatile("mma.sync.aligned.m16n8k16.row.col.f32.bf16.bf16.f32 " \
        "{%0,%1,%2,%3}, {%4,%5,%6,%7}, {%8,%9}, {%0,%1,%2,%3};" \
        : "+f"((c)[0]), "+f"((c)[1]), "+f"((c)[2]), "+f"((c)[3]) \
        : "r"((a)[0]), "r"((a)[1]), "r"((a)[2]), "r"((a)[3]), "r"(b0), "r"(b1))

// ordering: (dA,iA) < (dB,iB)  [strict, lowest index on ties]
static __device__ __forceinline__ bool lt(float dA, int iA, float dB, int iB) {
    return dA < dB || (dA == dB && iA < iB);
}
static __device__ __forceinline__ void ins2(float d, int i,
                                            float& bD, int& bI, float& sD, int& sI) {
    if (lt(d, i, bD, bI)) { sD = bD; sI = bI; bD = d; bI = i; }
    else if (lt(d, i, sD, sI)) { sD = d; sI = i; }
}

// bf16 dual-limb sp of a scalar (x = limb0 + limb1 + O(2^-18 x))
static __device__ __forceinline__ __nv_bfloat16 split_bf(float f, int sp) {
    __nv_bfloat16 h1 = __float2bfloat16_rn(f);
    if (sp == 0) return h1;
    return __float2bfloat16_rn(__fadd_rn(f, -__bfloat162float(h1)));
}

// ---------------------------------------------------------------- prep
__global__ void vq_prep(const float* __restrict__ emb) {
    int g = blockIdx.x * blockDim.x + threadIdx.x;   // 0..2047
    int k = g >> 1, half = g & 1;
    const float4* e4 = (const float4*)(emb + (size_t)k * DIMV + half * 64);
    unsigned char* base = g_eTp + (size_t)k * ROWB + half * 128;
    double s = 0.0;
#pragma unroll
    for (int i = 0; i < 16; ++i) {
        float4 v = e4[i];
        s += (double)__fmul_rn(v.x, v.x) + (double)__fmul_rn(v.y, v.y)
           + (double)__fmul_rn(v.z, v.z) + (double)__fmul_rn(v.w, v.w);
#pragma unroll
        for (int sp = 0; sp < 2; ++sp) {
            unsigned char* p = base + (size_t)sp * ET_SPLIT + i * 8;
            *(__nv_bfloat162*)(p)     = __halves2bfloat162(split_bf(v.x, sp), split_bf(v.y, sp));
            *(__nv_bfloat162*)(p + 4) = __halves2bfloat162(split_bf(v.z, sp), split_bf(v.w, sp));
        }
    }
    s += __shfl_xor_sync(0xffffffffu, s, 1);
    if (!half) { g_re[k] = (float)s; g_counts[k] = 0; }
    if (g == 0) { g_loss = 0.0; g_ticket = 0u; }
}

// ---------------------------------------------------------------- main
__global__ __launch_bounds__(TPB, 2)
void vq_main(const float* __restrict__ x, const float* __restrict__ emb,
             float* __restrict__ out, int out_size) {
    extern __shared__ __align__(16) char sm[];
    float*  sRE   = (float*)(sm + SM_RE);
    float*  sRX   = (float*)(sm + SM_RX);
    float*  sRedD = (float*)(sm + SM_REDD);
    int*    sRedI = (int*)  (sm + SM_REDI);
    double* sLoss = (double*)(sm + SM_LOSS);
    float*  sRed2 = (float*)(sm + SM_RED2);
    unsigned int* sFlag = (unsigned int*)(sm + SM_FLAG);

    const uint32_t smb = smem_u32(sm);
    const int tid = threadIdx.x, wid = tid >> 5, l = tid & 31;
    const int wm = wid & 3, wn = wid >> 2;          // 4 x 2 warp grid
    const size_t row0 = (size_t)blockIdx.x * RPB;

    // ---- stage x limbs (padded bf16) + fp64 row norms ----
    {
        int row = tid >> 1, half = tid & 1;
        const float4* xr = (const float4*)(x + (row0 + row) * DIMV + half * 64);
        char* base = sm + SM_XA + row * ROWB + half * 128;
        double s = 0.0;
#pragma unroll
        for (int i = 0; i < 16; ++i) {
            float4 v = xr[i];
            s += (double)__fmul_rn(v.x, v.x) + (double)__fmul_rn(v.y, v.y)
               + (double)__fmul_rn(v.z, v.z) + (double)__fmul_rn(v.w, v.w);
#pragma unroll
            for (int sp = 0; sp < 2; ++sp) {
                char* p = base + sp * XA_SPLIT + i * 8;
                *(__nv_bfloat162*)(p)     = __halves2bfloat162(split_bf(v.x, sp), split_bf(v.y, sp));
                *(__nv_bfloat162*)(p + 4) = __halves2bfloat162(split_bf(v.z, sp), split_bf(v.w, sp));
            }
        }
        s += __shfl_xor_sync(0xffffffffu, s, 1);
        if (!half) sRX[row] = (float)s;
    }
    for (int i = tid; i < KCODES; i += TPB) sRE[i] = g_re[i];
    __syncthreads();   // staging of A/rx visible

    float rxv[4];
#pragma unroll
    for (int s = 0; s < 4; ++s) rxv[s] = sRX[wm * 32 + (l >> 2) + s * 8];

    uint32_t aAddr[2][2];
#pragma unroll
    for (int sp = 0; sp < 2; ++sp)
#pragma unroll
        for (int mi = 0; mi < 2; ++mi)
            aAddr[sp][mi] = smb + SM_XA + sp * XA_SPLIT
                          + (wm * 32 + mi * 16 + (l & 15)) * ROWB + ((l >> 4) & 1) * 16;
    uint32_t bOff[2][2];   // [limb][n16 group]
#pragma unroll
    for (int sp = 0; sp < 2; ++sp)
#pragma unroll
        for (int g = 0; g < 2; ++g)
            bOff[sp][g] = sp * B_SPLIT
                        + (wn * 32 + g * 16 + (l & 7) + ((l >> 4) & 1) * 8) * ROWB
                        + ((l >> 3) & 1) * 16;

    float bestD[4], secD[4];
    int   bestI[4], secI[4];
#pragma unroll
    for (int s = 0; s < 4; ++s) {
        bestD[s] = secD[s] = 3.402823466e38f;
        bestI[s] = secI[s] = 0x7fffffff;
    }

#pragma unroll 1
    for (int c = 0; c < NCH; ++c) {
        // ---- load B chunk c (both limbs) into the single buffer ----
        {
            uint32_t dst = smb + SM_B;
            const char* src = (const char*)g_eTp + (size_t)c * CPC * ROWB;
            for (int i = tid; i < B_BUF / 16; i += TPB) {
                int s = i / (B_SPLIT / 16), r = i - s * (B_SPLIT / 16);
                cp_async16(dst + i * 16, src + (size_t)s * ET_SPLIT + r * 16);
            }
            CP_COMMIT();
            CP_WAIT0();
        }
        __syncthreads();                 // buffer visible to all warps
        uint32_t bB = smb + SM_B;

        float acc[2][4][4];
#pragma unroll
        for (int mi = 0; mi < 2; ++mi)
#pragma unroll
            for (int ni = 0; ni < 4; ++ni)
#pragma unroll
                for (int q = 0; q < 4; ++q) acc[mi][ni][q] = 0.f;

#pragma unroll
        for (int ks = 0; ks < 8; ++ks) {
            uint32_t A0[2][4], A1[2][4], B0[2][4], B1[2][4];
#pragma unroll
            for (int mi = 0; mi < 2; ++mi) {
                LDSM4(A0[mi], aAddr[0][mi] + ks * 32);
                LDSM4(A1[mi], aAddr[1][mi] + ks * 32);
            }
#pragma unroll
            for (int g = 0; g < 2; ++g) LDSM4(B0[g], bB + bOff[0][g] + ks * 32);
            // pass (x1,e1) and (x2,e1) on B limb0
#pragma unroll
            for (int mi = 0; mi < 2; ++mi)
#pragma unroll
                for (int ni = 0; ni < 4; ++ni) {
                    int g = ni >> 1, h = (ni & 1) * 2;
                    MMA16816(acc[mi][ni], A0[mi], B0[g][h], B0[g][h + 1]);
                    MMA16816(acc[mi][ni], A1[mi], B0[g][h], B0[g][h + 1]);
                }
#pragma unroll
            for (int g = 0; g < 2; ++g) LDSM4(B1[g], bB + bOff[1][g] + ks * 32);
            // pass (x1,e2) on B limb1
#pragma unroll
            for (int mi = 0; mi < 2; ++mi)
#pragma unroll
                for (int ni = 0; ni < 4; ++ni) {
                    int g = ni >> 1, h = (ni & 1) * 2;
                    MMA16816(acc[mi][ni], A0[mi], B1[g][h], B1[g][h + 1]);
                }
        }

        // epilogue: reference-rounded distance + running top-2
        int cb = c * CPC + wn * 32;
#pragma unroll
        for (int mi = 0; mi < 2; ++mi) {
#pragma unroll
            for (int ni = 0; ni < 4; ++ni) {
                int code = cb + ni * 8 + 2 * (l & 3);
                float re0 = sRE[code], re1 = sRE[code + 1];
                int s0 = mi * 2, s1 = mi * 2 + 1;
                float d;
                d = __fadd_rn(__fadd_rn(rxv[s0], re0), __fmul_rn(acc[mi][ni][0], -2.0f));
                ins2(d, code,     bestD[s0], bestI[s0], secD[s0], secI[s0]);
                d = __fadd_rn(__fadd_rn(rxv[s0], re1), __fmul_rn(acc[mi][ni][1], -2.0f));
                ins2(d, code + 1, bestD[s0], bestI[s0], secD[s0], secI[s0]);
                d = __fadd_rn(__fadd_rn(rxv[s1], re0), __fmul_rn(acc[mi][ni][2], -2.0f));
                ins2(d, code,     bestD[s1], bestI[s1], secD[s1], secI[s1]);
                d = __fadd_rn(__fadd_rn(rxv[s1], re1), __fmul_rn(acc[mi][ni][3], -2.0f));
                ins2(d, code + 1, bestD[s1], bestI[s1], secD[s1], secI[s1]);
            }
        }
        __syncthreads();                 // all readers done before next chunk's loads
    }

    // ---- top-2 merge across lanes (bfly over l&3) ----
#pragma unroll
    for (int s = 0; s < 4; ++s) {
#pragma unroll
        for (int m = 1; m <= 2; m <<= 1) {
            float obD = __shfl_xor_sync(0xffffffffu, bestD[s], m);
            int   obI = __shfl_xor_sync(0xffffffffu, bestI[s], m);
            float osD = __shfl_xor_sync(0xffffffffu, secD[s], m);
            int   osI = __shfl_xor_sync(0xffffffffu, secI[s], m);
            ins2(obD, obI, bestD[s], bestI[s], secD[s], secI[s]);
            ins2(osD, osI, bestD[s], bestI[s], secD[s], secI[s]);
        }
    }
    if ((l & 3) == 0) {
#pragma unroll
        for (int s = 0; s < 4; ++s) {
            int r = wm * 32 + (l >> 2) + s * 8;
            sRedD[(r * 2 + wn) * 2]     = bestD[s];
            sRedD[(r * 2 + wn) * 2 + 1] = secD[s];
            sRedI[(r * 2 + wn) * 2]     = bestI[s];
            sRedI[(r * 2 + wn) * 2 + 1] = secI[s];
        }
    }
    __syncthreads();

    // ---- per-row final: EXACT fp32 recheck of ALL 4 candidates ----
    if (tid < RPB) {
        const float4* xr = (const float4*)(x + (row0 + tid) * DIMV);
        float rx = sRX[tid];
        float bD = 3.402823466e38f;
        int   bi = 0x7fffffff;
#pragma unroll
        for (int t = 0; t < 4; ++t) {
            int cd = sRedI[tid * 4 + t];
            const float4* er = (const float4*)(emb + (size_t)cd * DIMV);
            float a0 = 0.f, a1 = 0.f, a2 = 0.f, a3 = 0.f;
#pragma unroll 8
            for (int j = 0; j < 32; ++j) {
                float4 xv = xr[j], ev = er[j];
                a0 = __fmaf_rn(xv.x, ev.x, a0);
                a1 = __fmaf_rn(xv.y, ev.y, a1);
                a2 = __fmaf_rn(xv.z, ev.z, a2);
                a3 = __fmaf_rn(xv.w, ev.w, a3);
            }
            float m = __fadd_rn(__fadd_rn(a0, a1), __fadd_rn(a2, a3));
            float d = __fadd_rn(__fadd_rn(rx, sRE[cd]), __fmul_rn(m, -2.0f));
            if (lt(d, cd, bD, bi)) { bD = d; bi = cd; }
        }
        sRedI[tid * 4] = bi;             // reuse as per-row best index
        atomicAdd(&g_counts[bi], 1);
    }
    __syncthreads();

    // ---- fused output: STE-rounded gather + fp64 loss partial ----
    double ls = 0.0;
    {
        const float4* xin4 = (const float4*)(x + row0 * DIMV);
        float4*       o4   = (float4*)(out + row0 * DIMV);
        const float4* e4   = (const float4*)emb;
        for (int i = tid; i < RPB * (DIMV / 4); i += TPB) {
            int rr  = i >> 5;
            int col = i & 31;
            float4 q  = e4[(size_t)sRedI[rr * 4] * 32 + col];
            float4 xv = xin4[i];
            float4 o;
            o.x = __fadd_rn(xv.x, __fadd_rn(q.x, -xv.x));
            o.y = __fadd_rn(xv.y, __fadd_rn(q.y, -xv.y));
            o.z = __fadd_rn(xv.z, __fadd_rn(q.z, -xv.z));
            o.w = __fadd_rn(xv.w, __fadd_rn(q.w, -xv.w));
            o4[i] = o;
            double dx = (double)q.x - xv.x, dy = (double)q.y - xv.y;
            double dz = (double)q.z - xv.z, dw = (double)q.w - xv.w;
            ls += dx * dx + dy * dy + dz * dz + dw * dw;
        }
    }
#pragma unroll
    for (int o = 16; o > 0; o >>= 1) ls += __shfl_down_sync(0xffffffffu, ls, o);
    if (l == 0) sLoss[wid] = ls;
    __syncthreads();
    if (tid == 0) {
        double t = 0.0;
#pragma unroll
        for (int i = 0; i < 8; ++i) t += sLoss[i];
        atomicAdd(&g_loss, t);
        __threadfence();
        unsigned int tk = atomicAdd(&g_ticket, 1u);
        sFlag[0] = (tk == (unsigned int)(NBLOCKS - 1)) ? 1u : 0u;
    }
    __syncthreads();

    // ---- fused finalize (last block only): perplexity + loss scalars ----
    if (sFlag[0]) {
        __threadfence();
        float acc = 0.f;
        for (int k = tid; k < KCODES; k += TPB) {
            float p = (float)__ldcg(&g_counts[k]) * (1.0f / (float)N_ROWS);
            acc += p * logf(p + 1e-10f);
        }
#pragma unroll
        for (int o = 16; o > 0; o >>= 1) acc += __shfl_down_sync(0xffffffffu, acc, o);
        if (l == 0) sRed2[wid] = acc;
        __syncthreads();
        if (tid == 0) {
            float s = 0.f;
#pragma unroll
            for (int i = 0; i < 8; ++i) s += sRed2[i];
            double lv = __ldcg(&g_loss);
            out[out_size - 2] = (float)(1.25 * (lv / (double)(N_ROWS * DIMV)));
            out[out_size - 1] = expf(-s);
        }
    }
}

// ----------------------------------------------------------------
extern "C" void kernel_launch(void* const* d_in, const int* in_sizes, int n_in,
                              void* d_out, int out_size) {
    const float* x   = (const float*)d_in[0];
    const float* emb = (const float*)d_in[1];
    float*       out = (float*)d_out;
    (void)in_sizes; (void)n_in;

    cudaFuncSetAttribute(vq_main, cudaFuncAttributeMaxDynamicSharedMemorySize,
                         SMEM_TOTAL);

    vq_prep<<<8, 256>>>(emb);
    vq_main<<<NBLOCKS, TPB, SMEM_TOTAL>>>(x, emb, out, out_size);
}